// round 1
// baseline (speedup 1.0000x reference)
#include <cuda_runtime.h>
#include <math.h>

#define NBATCH 256
#define MG     256
#define NTOT   (NBATCH*MG)      // 65536 nodes
#define KNN    15
#define FIN    7
#define CC     128
#define CST    384              // stride of HC buffer: [h | a1 | a2]
#define C2     768
#define LEAKY  0.01f
#define AGG_NORM (1.0f/15.0f)   // deg==15 for every node -> norm constant

// ---------------- scratch (static device allocations; no cudaMalloc) --------
__device__ int   g_knn[NTOT*KNN];
__device__ float g_hc0[NTOT*21];                 // layer-1 input: [x|Ax|A2x], stride 21
__device__ float g_hca[(size_t)NTOT*CST];
__device__ float g_hcb[(size_t)NTOT*CST];
__device__ float g_g1[NBATCH*C2];
__device__ float g_g2[NBATCH*C2];

// ---------------- kNN: one block per graph ----------------------------------
__global__ void knn_kernel(const float* __restrict__ x, int* __restrict__ knn) {
    __shared__ float4 pos[MG];
    __shared__ float  sq[MG];
    int g = blockIdx.x, t = threadIdx.x;
    const float* xr = x + (size_t)(g*MG + t)*FIN;
    float4 p = make_float4(xr[0], xr[1], xr[2], xr[3]);
    pos[t] = p;
    sq[t]  = p.x*p.x + p.y*p.y + p.z*p.z + p.w*p.w;
    __syncthreads();

    float bd[KNN]; int bi[KNN];
#pragma unroll
    for (int i = 0; i < KNN; i++) { bd[i] = 1e30f; bi[i] = 0; }
    float mysq = sq[t];
    for (int j = 0; j < MG; j++) {
        if (j == t) continue;
        float4 q = pos[j];
        float d = mysq + sq[j] - 2.0f*(p.x*q.x + p.y*q.y + p.z*q.z + p.w*q.w);
        if (d < bd[KNN-1]) {
            int k = KNN-1;
            while (k > 0 && bd[k-1] > d) { bd[k] = bd[k-1]; bi[k] = bi[k-1]; k--; }
            bd[k] = d; bi[k] = j;
        }
    }
    int* out = knn + (size_t)(g*MG + t)*KNN;
#pragma unroll
    for (int i = 0; i < KNN; i++) out[i] = g*MG + bi[i];
}

// ---------------- small helpers ---------------------------------------------
__global__ void copy_x_kernel(const float* __restrict__ x, float* __restrict__ hc0) {
    int i = blockIdx.x*blockDim.x + threadIdx.x;
    if (i < NTOT*FIN) {
        int n = i / FIN, f = i % FIN;
        hc0[(size_t)n*21 + f] = x[i];
    }
}

// mean-over-15-neighbors for 7-wide features
__global__ void agg_small(const float* __restrict__ src, int ss,
                          float* __restrict__ dst, int ds,
                          const int* __restrict__ knn) {
    int n = blockIdx.x*blockDim.x + threadIdx.x;
    if (n >= NTOT) return;
    const int* nb = knn + (size_t)n*KNN;
    float acc[FIN] = {};
#pragma unroll
    for (int k = 0; k < KNN; k++) {
        const float* r = src + (size_t)nb[k]*ss;
#pragma unroll
        for (int f = 0; f < FIN; f++) acc[f] += r[f];
    }
#pragma unroll
    for (int f = 0; f < FIN; f++) dst[(size_t)n*ds + f] = acc[f]*AGG_NORM;
}

// mean-over-15-neighbors for 128-wide features living inside stride-384 buffer
__global__ void agg128(const float* __restrict__ src, float* __restrict__ dst,
                       const int* __restrict__ knn) {
    int n = blockIdx.x, c = threadIdx.x;
    const int* nb = knn + (size_t)n*KNN;
    float s = 0.0f;
#pragma unroll
    for (int k = 0; k < KNN; k++) s += __ldg(&src[(size_t)nb[k]*CST + c]);
    dst[(size_t)n*CST + c] = s*AGG_NORM;
}

// ---------------- generic tiled SGEMM: C = act(A@B + bias) ------------------
// A: MxK (row stride lda), B: KxN row-major, C: MxN (row stride ldc)
template<int BM, int BN, int BK, int TM, int TN>
__global__ void sgemm_act(const float* __restrict__ A, int lda,
                          const float* __restrict__ B,
                          const float* __restrict__ bias,
                          float* __restrict__ C, int ldc,
                          int M, int N, int K, int act) {
    constexpr int THREADS = (BM/TM)*(BN/TN);
    __shared__ float As[BK][BM+1];
    __shared__ float Bs[BK][BN+1];
    const int bm = blockIdx.y * BM;
    const int bn = blockIdx.x * BN;
    const int tid = threadIdx.x;
    const int tx = tid % (BN/TN);
    const int ty = tid / (BN/TN);

    float acc[TM][TN] = {};
    for (int k0 = 0; k0 < K; k0 += BK) {
        // load A tile (BM x BK)
#pragma unroll
        for (int i = tid; i < BM*BK; i += THREADS) {
            int r = i / BK, c = i % BK;
            int gr = bm + r, gk = k0 + c;
            float v = 0.0f;
            if (gk < K && gr < M) v = A[(size_t)gr*lda + gk];
            As[c][r] = v;
        }
        // load B tile (BK x BN)
#pragma unroll
        for (int i = tid; i < BK*BN; i += THREADS) {
            int r = i / BN, c = i % BN;
            int gk = k0 + r, gc = bn + c;
            float v = 0.0f;
            if (gk < K && gc < N) v = B[(size_t)gk*N + gc];
            Bs[r][c] = v;
        }
        __syncthreads();
#pragma unroll
        for (int kk = 0; kk < BK; kk++) {
            float ra[TM], rb[TN];
#pragma unroll
            for (int i = 0; i < TM; i++) ra[i] = As[kk][ty*TM + i];
#pragma unroll
            for (int j = 0; j < TN; j++) rb[j] = Bs[kk][tx*TN + j];
#pragma unroll
            for (int i = 0; i < TM; i++)
#pragma unroll
                for (int j = 0; j < TN; j++) acc[i][j] += ra[i]*rb[j];
        }
        __syncthreads();
    }
#pragma unroll
    for (int i = 0; i < TM; i++) {
        int gr = bm + ty*TM + i;
        if (gr >= M) continue;
#pragma unroll
        for (int j = 0; j < TN; j++) {
            int gc = bn + tx*TN + j;
            if (gc >= N) continue;
            float v = acc[i][j] + bias[gc];
            if (act == 1) v = (v > 0.0f) ? v : LEAKY*v;
            C[(size_t)gr*ldc + gc] = v;
        }
    }
}

// ---------------- per-graph mean/max pool into g -----------------------------
__global__ void pool_kernel(const float* __restrict__ h, float* __restrict__ g, int layer) {
    int b = blockIdx.x, c = threadIdx.x;   // 128 threads
    const float* base = h + (size_t)b*MG*CST + c;
    float s = 0.0f, mx = -1e30f;
    for (int m = 0; m < MG; m++) {
        float v = base[(size_t)m*CST];
        s += v; mx = fmaxf(mx, v);
    }
    g[b*C2 + layer*256 + c]       = s*(1.0f/MG);
    g[b*C2 + layer*256 + 128 + c] = mx;
}

// ---------------- batch-norm over batch dim (two-pass, 1 block x 768) -------
__global__ void bn_kernel(float* __restrict__ g, const float* __restrict__ gamma,
                          const float* __restrict__ beta) {
    int c = threadIdx.x;   // 768 threads
    float s = 0.0f;
    for (int r = 0; r < NBATCH; r++) s += g[r*C2 + c];
    float mu = s*(1.0f/NBATCH);
    float v = 0.0f;
    for (int r = 0; r < NBATCH; r++) { float d = g[r*C2 + c] - mu; v += d*d; }
    v *= (1.0f/NBATCH);
    float sc = rsqrtf(v + 1e-5f)*gamma[c];
    float bt = beta[c];
    for (int r = 0; r < NBATCH; r++) g[r*C2 + c] = (g[r*C2 + c] - mu)*sc + bt;
}

__global__ void tanh_kernel(float* __restrict__ y) {
    int b = threadIdx.x;
    if (b < NBATCH) {
        y[b*3 + 0] = tanhf(y[b*3 + 0]);
        y[b*3 + 1] = tanhf(y[b*3 + 1]);
    }
}

// ---------------- launch ------------------------------------------------------
extern "C" void kernel_launch(void* const* d_in, const int* in_sizes, int n_in,
                              void* d_out, int out_size) {
    const float* x   = (const float*)d_in[0];
    const float* Wc1 = (const float*)d_in[1];  const float* bc1 = (const float*)d_in[2];
    const float* Wc2 = (const float*)d_in[3];  const float* bc2 = (const float*)d_in[4];
    const float* Wc3 = (const float*)d_in[5];  const float* bc3 = (const float*)d_in[6];
    const float* bng = (const float*)d_in[7];  const float* bnb = (const float*)d_in[8];
    const float* Wm[5]; const float* bm[5];
    for (int i = 0; i < 5; i++) { Wm[i] = (const float*)d_in[9+2*i]; bm[i] = (const float*)d_in[10+2*i]; }
    const float* Wo = (const float*)d_in[19];  const float* bo = (const float*)d_in[20];
    float* y = (float*)d_out;

    int*   knn; float *hc0, *hca, *hcb, *g1, *g2;
    cudaGetSymbolAddress((void**)&knn, g_knn);
    cudaGetSymbolAddress((void**)&hc0, g_hc0);
    cudaGetSymbolAddress((void**)&hca, g_hca);
    cudaGetSymbolAddress((void**)&hcb, g_hcb);
    cudaGetSymbolAddress((void**)&g1,  g_g1);
    cudaGetSymbolAddress((void**)&g2,  g_g2);

    // 1. kNN graph construction (per-graph, smem positions)
    knn_kernel<<<NBATCH, MG>>>(x, knn);

    // 2. layer-1 input assembly: [x | Ax | A^2 x], stride 21
    copy_x_kernel<<<(NTOT*FIN + 255)/256, 256>>>(x, hc0);
    agg_small<<<NTOT/256, 256>>>(x,      FIN, hc0 + 7,  21, knn);
    agg_small<<<NTOT/256, 256>>>(hc0+7,  21,  hc0 + 14, 21, knn);

    // 3. conv layer 1: (N,21)@(21,128) + lrelu -> hca[:,0:128]
    sgemm_act<128,128,16,8,8><<<dim3(1, NTOT/128), 256>>>(
        hc0, 21, Wc1, bc1, hca, CST, NTOT, CC, 21, 1);
    pool_kernel<<<NBATCH, CC>>>(hca, g1, 0);

    // 4. conv layer 2
    agg128<<<NTOT, CC>>>(hca,       hca + 128, knn);
    agg128<<<NTOT, CC>>>(hca + 128, hca + 256, knn);
    sgemm_act<128,128,16,8,8><<<dim3(1, NTOT/128), 256>>>(
        hca, CST, Wc2, bc2, hcb, CST, NTOT, CC, CST, 1);
    pool_kernel<<<NBATCH, CC>>>(hcb, g1, 1);

    // 5. conv layer 3
    agg128<<<NTOT, CC>>>(hcb,       hcb + 128, knn);
    agg128<<<NTOT, CC>>>(hcb + 128, hcb + 256, knn);
    sgemm_act<128,128,16,8,8><<<dim3(1, NTOT/128), 256>>>(
        hcb, CST, Wc3, bc3, hca, CST, NTOT, CC, CST, 1);
    pool_kernel<<<NBATCH, CC>>>(hca, g1, 2);

    // 6. batch-norm over batch dimension
    bn_kernel<<<1, C2>>>(g1, bng, bnb);

    // 7. MLP: 5x (256,768)@(768,768)+lrelu, ping-pong g1/g2
    float* cur = g1; float* nxt = g2;
    for (int i = 0; i < 5; i++) {
        sgemm_act<64,64,16,4,4><<<dim3(C2/64, NBATCH/64), 256>>>(
            cur, C2, Wm[i], bm[i], nxt, C2, NBATCH, C2, C2, 1);
        float* t = cur; cur = nxt; nxt = t;
    }

    // 8. output head: (256,768)@(768,3), then tanh on cols 0,1
    sgemm_act<64,64,16,4,4><<<dim3(1, NBATCH/64), 256>>>(
        cur, C2, Wo, bo, y, 3, NBATCH, 3, C2, 0);
    tanh_kernel<<<1, NBATCH>>>(y);
}

// round 2
// speedup vs baseline: 1.8109x; 1.8109x over previous
#include <cuda_runtime.h>
#include <math.h>

#define NBATCH 256
#define MG     256
#define NTOT   (NBATCH*MG)      // 65536 nodes
#define KNN    15
#define FIN    7
#define CC     128
#define PST    384              // P buffer stride: [P0 | P1 | P2]
#define C2     768
#define LEAKY  0.01f
#define AGG_NORM (1.0f/15.0f)   // deg==15 for every node

// ---------------- scratch ----------------------------------------------------
__device__ int   g_knn[NTOT*KNN];
__device__ float g_P[(size_t)NTOT*PST];   // projections h@[W0|W1|W2]
__device__ float g_t[(size_t)NTOT*CC];    // P1 + A*P2
__device__ float g_h[(size_t)NTOT*CC];    // layer activations
__device__ float g_g1[NBATCH*C2];
__device__ float g_g2[NBATCH*C2];

// ---------------- kNN: one block per graph ------------------------------------
__global__ void knn_kernel(const float* __restrict__ x, int* __restrict__ knn) {
    __shared__ float4 pos[MG];
    __shared__ float  sq[MG];
    int g = blockIdx.x, t = threadIdx.x;
    const float* xr = x + (size_t)(g*MG + t)*FIN;
    float4 p = make_float4(xr[0], xr[1], xr[2], xr[3]);
    pos[t] = p;
    sq[t]  = p.x*p.x + p.y*p.y + p.z*p.z + p.w*p.w;
    __syncthreads();

    float bd[KNN]; int bi[KNN];
#pragma unroll
    for (int i = 0; i < KNN; i++) { bd[i] = 1e30f; bi[i] = 0; }
    float mysq = sq[t];
    for (int j = 0; j < MG; j++) {
        if (j == t) continue;
        float4 q = pos[j];
        float d = mysq + sq[j] - 2.0f*(p.x*q.x + p.y*q.y + p.z*q.z + p.w*q.w);
        if (d < bd[KNN-1]) {
            int k = KNN-1;
            while (k > 0 && bd[k-1] > d) { bd[k] = bd[k-1]; bi[k] = bi[k-1]; k--; }
            bd[k] = d; bi[k] = j;
        }
    }
    int* out = knn + (size_t)(g*MG + t)*KNN;
#pragma unroll
    for (int i = 0; i < KNN; i++) out[i] = g*MG + bi[i];
}

// ---------------- layer-1 projection: P = x(N,7) @ Wcat(7,384) ----------------
__global__ void conv1_kernel(const float* __restrict__ x,
                             const float* __restrict__ Wc,  // (3,7,128)
                             float* __restrict__ P) {
    __shared__ float xs[64*FIN];
    int b0 = blockIdx.x*64;
    int c = threadIdx.x;                 // 0..383
    for (int i = c; i < 64*FIN; i += 384) xs[i] = x[(size_t)b0*FIN + i];
    float w[FIN];
    int k = c >> 7, cc = c & 127;
#pragma unroll
    for (int f = 0; f < FIN; f++) w[f] = Wc[(k*FIN + f)*CC + cc];
    __syncthreads();
    for (int m = 0; m < 64; m++) {
        float acc = 0.0f;
#pragma unroll
        for (int f = 0; f < FIN; f++) acc += xs[m*FIN + f]*w[f];
        P[(size_t)(b0 + m)*PST + c] = acc;
    }
}

// ---------------- agg pass 1: t = P1 + A*P2 -----------------------------------
#define NPB 4   // nodes per block
__global__ void agg1_kernel(const float* __restrict__ P, const int* __restrict__ knn,
                            float* __restrict__ t) {
    __shared__ int nb[NPB][KNN];
    int nl = threadIdx.x >> 7;           // local node
    int c  = threadIdx.x & 127;
    int n  = blockIdx.x*NPB + nl;
    if (c < KNN) nb[nl][c] = knn[(size_t)n*KNN + c];
    __syncthreads();
    float s = 0.0f;
#pragma unroll
    for (int k = 0; k < KNN; k++) s += __ldg(&P[(size_t)nb[nl][k]*PST + 256 + c]);
    t[(size_t)n*CC + c] = P[(size_t)n*PST + 128 + c] + s*AGG_NORM;
}

// ---------------- agg pass 2: h = lrelu(P0 + A*t + b) --------------------------
__global__ void agg2_kernel(const float* __restrict__ P, const float* __restrict__ t,
                            const int* __restrict__ knn, const float* __restrict__ bias,
                            float* __restrict__ h) {
    __shared__ int nb[NPB][KNN];
    int nl = threadIdx.x >> 7;
    int c  = threadIdx.x & 127;
    int n  = blockIdx.x*NPB + nl;
    if (c < KNN) nb[nl][c] = knn[(size_t)n*KNN + c];
    __syncthreads();
    float s = 0.0f;
#pragma unroll
    for (int k = 0; k < KNN; k++) s += __ldg(&t[(size_t)nb[nl][k]*CC + c]);
    float v = P[(size_t)n*PST + c] + s*AGG_NORM + bias[c];
    h[(size_t)n*CC + c] = (v > 0.0f) ? v : LEAKY*v;
}

// ---------------- double-buffered vectorized SGEMM -----------------------------
// C[M,N] = act(A[M,K] @ B + bias). SLICED: B is 3 stacked (K x BN) slices,
// grid.x selects slice; else B is K x ldb row-major shared across grid.x.
template<int BM,int BN,int BK,int TM,int TN,bool SLICED>
__global__ void __launch_bounds__((BM/TM)*(BN/TN))
sgemm_k(const float* __restrict__ A, int lda,
        const float* __restrict__ B, int ldb,
        const float* __restrict__ bias,
        float* __restrict__ C, int ldc,
        int K, int act) {
    constexpr int THREADS = (BM/TM)*(BN/TN);
    constexpr int NA = (BM*BK/4)/THREADS;
    constexpr int NB = (BK*BN/4)/THREADS;
    __shared__ float As[2][BK][BM];
    __shared__ float Bs[2][BK][BN];
    const int bm = blockIdx.y*BM;
    const int cb = blockIdx.x*BN;
    const float* Bp = SLICED ? (B + (size_t)blockIdx.x*K*BN) : (B + cb);
    const int ldbe = SLICED ? BN : ldb;
    const int tid = threadIdx.x;
    const int tx = tid % (BN/TN);
    const int ty = tid / (BN/TN);

    float4 pa[NA], pb[NB];

    auto fetch = [&](int k0) {
#pragma unroll
        for (int i = 0; i < NA; i++) {
            int e = tid + i*THREADS;
            int row = e/(BK/4), c4 = e%(BK/4);
            pa[i] = *reinterpret_cast<const float4*>(A + (size_t)(bm+row)*lda + k0 + c4*4);
        }
#pragma unroll
        for (int i = 0; i < NB; i++) {
            int e = tid + i*THREADS;
            int row = e/(BN/4), c4 = e%(BN/4);
            pb[i] = *reinterpret_cast<const float4*>(Bp + (size_t)(k0+row)*ldbe + c4*4);
        }
    };
    auto store = [&](int buf) {
#pragma unroll
        for (int i = 0; i < NA; i++) {
            int e = tid + i*THREADS;
            int row = e/(BK/4), c4 = e%(BK/4);
            As[buf][c4*4+0][row] = pa[i].x;
            As[buf][c4*4+1][row] = pa[i].y;
            As[buf][c4*4+2][row] = pa[i].z;
            As[buf][c4*4+3][row] = pa[i].w;
        }
#pragma unroll
        for (int i = 0; i < NB; i++) {
            int e = tid + i*THREADS;
            int row = e/(BN/4), c4 = e%(BN/4);
            *reinterpret_cast<float4*>(&Bs[buf][row][c4*4]) = pb[i];
        }
    };

    float acc[TM][TN] = {};
    fetch(0); store(0); __syncthreads();
    const int nk = K/BK;
    for (int kt = 0; kt < nk; kt++) {
        int buf = kt & 1;
        if (kt + 1 < nk) fetch((kt+1)*BK);
#pragma unroll
        for (int kk = 0; kk < BK; kk++) {
            float ra[TM], rb[TN];
#pragma unroll
            for (int i = 0; i < TM; i++) ra[i] = As[buf][kk][ty*TM + i];
#pragma unroll
            for (int j = 0; j < TN; j++) rb[j] = Bs[buf][kk][tx*TN + j];
#pragma unroll
            for (int i = 0; i < TM; i++)
#pragma unroll
                for (int j = 0; j < TN; j++) acc[i][j] += ra[i]*rb[j];
        }
        if (kt + 1 < nk) { store(1 - buf); __syncthreads(); }
    }
#pragma unroll
    for (int i = 0; i < TM; i++) {
        int gr = bm + ty*TM + i;
#pragma unroll
        for (int j = 0; j < TN; j += 4) {
            float4 v;
            float* vv = reinterpret_cast<float*>(&v);
#pragma unroll
            for (int q = 0; q < 4; q++) {
                int gc = cb + tx*TN + j + q;
                float u = acc[i][j+q];
                if (bias) u += bias[gc];
                if (act)  u = (u > 0.0f) ? u : LEAKY*u;
                vv[q] = u;
            }
            *reinterpret_cast<float4*>(&C[(size_t)gr*ldc + cb + tx*TN + j]) = v;
        }
    }
}

// ---------------- per-graph mean/max pool --------------------------------------
__global__ void pool_kernel(const float* __restrict__ h, float* __restrict__ g, int layer) {
    int b = blockIdx.x, c = threadIdx.x;  // 128 threads
    const float* base = h + (size_t)b*MG*CC + c;
    float s = 0.0f, mx = -1e30f;
    for (int m = 0; m < MG; m++) {
        float v = base[(size_t)m*CC];
        s += v; mx = fmaxf(mx, v);
    }
    g[b*C2 + layer*256 + c]       = s*(1.0f/MG);
    g[b*C2 + layer*256 + 128 + c] = mx;
}

// ---------------- batch-norm: one block per channel -----------------------------
__global__ void bn_kernel(float* __restrict__ g, const float* __restrict__ gamma,
                          const float* __restrict__ beta) {
    __shared__ float red[256];
    int c = blockIdx.x, t = threadIdx.x;   // 256 threads
    float v = g[t*C2 + c];
    red[t] = v; __syncthreads();
    for (int s = 128; s > 0; s >>= 1) { if (t < s) red[t] += red[t+s]; __syncthreads(); }
    float mu = red[0]*(1.0f/NBATCH);
    __syncthreads();
    float d = v - mu;
    red[t] = d*d; __syncthreads();
    for (int s = 128; s > 0; s >>= 1) { if (t < s) red[t] += red[t+s]; __syncthreads(); }
    float var = red[0]*(1.0f/NBATCH);
    float sc = rsqrtf(var + 1e-5f)*gamma[c];
    g[t*C2 + c] = (v - mu)*sc + beta[c];
}

// ---------------- head: (256,768)@(768,3) + tanh on cols 0,1 --------------------
__global__ void head_kernel(const float* __restrict__ g, const float* __restrict__ Wo,
                            const float* __restrict__ bo, float* __restrict__ y) {
    int b = blockIdx.x;
    int w = threadIdx.y;   // 0..2
    int l = threadIdx.x;   // 0..31
    float s = 0.0f;
    for (int f = l; f < C2; f += 32) s += g[b*C2 + f]*Wo[f*3 + w];
#pragma unroll
    for (int o = 16; o; o >>= 1) s += __shfl_down_sync(0xffffffff, s, o);
    if (l == 0) {
        float v = s + bo[w];
        if (w < 2) v = tanhf(v);
        y[b*3 + w] = v;
    }
}

// ---------------- launch ---------------------------------------------------------
extern "C" void kernel_launch(void* const* d_in, const int* in_sizes, int n_in,
                              void* d_out, int out_size) {
    const float* x   = (const float*)d_in[0];
    const float* Wc1 = (const float*)d_in[1];  const float* bc1 = (const float*)d_in[2];
    const float* Wc2 = (const float*)d_in[3];  const float* bc2 = (const float*)d_in[4];
    const float* Wc3 = (const float*)d_in[5];  const float* bc3 = (const float*)d_in[6];
    const float* bng = (const float*)d_in[7];  const float* bnb = (const float*)d_in[8];
    const float* Wm[5]; const float* bm[5];
    for (int i = 0; i < 5; i++) { Wm[i] = (const float*)d_in[9+2*i]; bm[i] = (const float*)d_in[10+2*i]; }
    const float* Wo = (const float*)d_in[19];  const float* bo = (const float*)d_in[20];
    float* y = (float*)d_out;

    int* knn; float *P, *t, *h, *g1, *g2;
    cudaGetSymbolAddress((void**)&knn, g_knn);
    cudaGetSymbolAddress((void**)&P,   g_P);
    cudaGetSymbolAddress((void**)&t,   g_t);
    cudaGetSymbolAddress((void**)&h,   g_h);
    cudaGetSymbolAddress((void**)&g1,  g_g1);
    cudaGetSymbolAddress((void**)&g2,  g_g2);

    // 1. kNN
    knn_kernel<<<NBATCH, MG>>>(x, knn);

    // 2. layer 1: project, aggregate, activate, pool
    conv1_kernel<<<NTOT/64, 384>>>(x, Wc1, P);
    agg1_kernel<<<NTOT/NPB, NPB*128>>>(P, knn, t);
    agg2_kernel<<<NTOT/NPB, NPB*128>>>(P, t, knn, bc1, h);
    pool_kernel<<<NBATCH, CC>>>(h, g1, 0);

    // 3. layer 2: P = h @ [W0|W1|W2] (sliced), aggregate, pool
    sgemm_k<128,128,16,8,8,true><<<dim3(3, NTOT/128), 256>>>(
        h, CC, Wc2, 0, nullptr, P, PST, CC, 0);
    agg1_kernel<<<NTOT/NPB, NPB*128>>>(P, knn, t);
    agg2_kernel<<<NTOT/NPB, NPB*128>>>(P, t, knn, bc2, h);
    pool_kernel<<<NBATCH, CC>>>(h, g1, 1);

    // 4. layer 3
    sgemm_k<128,128,16,8,8,true><<<dim3(3, NTOT/128), 256>>>(
        h, CC, Wc3, 0, nullptr, P, PST, CC, 0);
    agg1_kernel<<<NTOT/NPB, NPB*128>>>(P, knn, t);
    agg2_kernel<<<NTOT/NPB, NPB*128>>>(P, t, knn, bc3, h);
    pool_kernel<<<NBATCH, CC>>>(h, g1, 2);

    // 5. batch-norm
    bn_kernel<<<C2, 256>>>(g1, bng, bnb);

    // 6. MLP x5
    float* cur = g1; float* nxt = g2;
    for (int i = 0; i < 5; i++) {
        sgemm_k<32,64,16,4,4,false><<<dim3(C2/64, NBATCH/32), 128>>>(
            cur, C2, Wm[i], C2, bm[i], nxt, C2, C2, 1);
        float* tmp = cur; cur = nxt; nxt = tmp;
    }

    // 7. head + fused tanh
    head_kernel<<<NBATCH, dim3(32,3)>>>(cur, Wo, bo, y);
}

// round 3
// speedup vs baseline: 1.8819x; 1.0392x over previous
#include <cuda_runtime.h>
#include <math.h>

#define NBATCH 256
#define MG     256
#define NTOT   (NBATCH*MG)      // 65536 nodes
#define KNN    15
#define FIN    7
#define CC     128
#define PST    384              // P buffer stride: [P0 | P1 | P2]
#define C2     768
#define LEAKY  0.01f
#define AGG_NORM (1.0f/15.0f)   // deg==15 for every node

// ---------------- scratch ----------------------------------------------------
__device__ int   g_knn[NTOT*KNN];
__device__ float g_P[(size_t)NTOT*PST];   // projections h@[W0|W1|W2]
__device__ float g_h[(size_t)NTOT*CC];    // layer activations
__device__ float g_g1[NBATCH*C2];
__device__ float g_g2[NBATCH*C2];

// ---------------- kNN: one block per graph ------------------------------------
__global__ void knn_kernel(const float* __restrict__ x, int* __restrict__ knn) {
    __shared__ float4 pos[MG];
    __shared__ float  sq[MG];
    int g = blockIdx.x, t = threadIdx.x;
    const float* xr = x + (size_t)(g*MG + t)*FIN;
    float4 p = make_float4(xr[0], xr[1], xr[2], xr[3]);
    pos[t] = p;
    sq[t]  = p.x*p.x + p.y*p.y + p.z*p.z + p.w*p.w;
    __syncthreads();

    float bd[KNN]; int bi[KNN];
#pragma unroll
    for (int i = 0; i < KNN; i++) { bd[i] = 1e30f; bi[i] = 0; }
    float mysq = sq[t];
    for (int j = 0; j < MG; j++) {
        if (j == t) continue;
        float4 q = pos[j];
        float d = mysq + sq[j] - 2.0f*(p.x*q.x + p.y*q.y + p.z*q.z + p.w*q.w);
        if (d < bd[KNN-1]) {
            int k = KNN-1;
            while (k > 0 && bd[k-1] > d) { bd[k] = bd[k-1]; bi[k] = bi[k-1]; k--; }
            bd[k] = d; bi[k] = j;
        }
    }
    int* out = knn + (size_t)(g*MG + t)*KNN;
#pragma unroll
    for (int i = 0; i < KNN; i++) out[i] = g*MG + bi[i];
}

// ---------------- fused TAGConv aggregate + activate + pool --------------------
// Block = (channel chunk of 32, graph). smem-resident two-hop aggregation.
//   L1=true : projections computed inline from x (K=7), Wc = (3,7,128)
//   L1=false: projections read from P (stride 384)
// Dynamic smem layout (floats):
//   s2 [0,8192)      : P2 chunk  (256 nodes x 32 ch)
//   st [8192,16384)  : t chunk
//   nbs[16384,20224) : local neighbor ids (int), 256x15
//   xs [20224,22272) : x graph (256 x 8, padded), L1 only
#define AGG_SMEM_FLOATS 22272
template<bool L1>
__global__ void __launch_bounds__(256)
tag_agg(const float* __restrict__ P, const float* __restrict__ x,
        const float* __restrict__ Wc, const int* __restrict__ knn,
        const float* __restrict__ bias, float* __restrict__ h,
        float* __restrict__ g, int layer) {
    extern __shared__ float sm[];
    float* s2 = sm;
    float* st = sm + 8192;
    int*   nbs = (int*)(sm + 16384);
    float* xs  = sm + 20224;

    const int c0   = blockIdx.x*32;
    const int gph  = blockIdx.y;
    const int base = gph*MG;
    const int tid  = threadIdx.x;
    const int c    = tid & 31;
    const int ng   = tid >> 5;

    // stage neighbor lists (pre-masked to local ids)
    for (int i = tid; i < MG*KNN; i += 256)
        nbs[i] = knn[(size_t)base*KNN + i] & (MG-1);

    float w0[FIN], w1[FIN], w2[FIN];
    if (L1) {
#pragma unroll
        for (int f = 0; f < FIN; f++) {
            w0[f] = Wc[(0*FIN + f)*CC + c0 + c];
            w1[f] = Wc[(1*FIN + f)*CC + c0 + c];
            w2[f] = Wc[(2*FIN + f)*CC + c0 + c];
        }
        for (int i = tid; i < MG*FIN; i += 256)
            xs[(i/FIN)*8 + (i%FIN)] = x[(size_t)base*FIN + i];
    }

    // stage P2 chunk (or compute it for layer 1)
    if (L1) {
        __syncthreads();   // xs ready
#pragma unroll 4
        for (int j = 0; j < 32; j++) {
            int n = ng*32 + j;
            float acc = 0.0f;
#pragma unroll
            for (int f = 0; f < FIN; f++) acc += xs[n*8 + f]*w2[f];
            s2[n*32 + c] = acc;
        }
    } else {
#pragma unroll 4
        for (int j = 0; j < 32; j++) {
            int n = ng*32 + j;
            s2[n*32 + c] = P[(size_t)(base + n)*PST + 256 + c0 + c];
        }
    }
    __syncthreads();

    // pass 1: t = P1 + A*P2
#pragma unroll 2
    for (int j = 0; j < 32; j++) {
        int n = ng*32 + j;
        const int* nbp = nbs + n*KNN;
        float s = 0.0f;
#pragma unroll
        for (int k = 0; k < KNN; k++) s += s2[nbp[k]*32 + c];
        float p1;
        if (L1) {
            p1 = 0.0f;
#pragma unroll
            for (int f = 0; f < FIN; f++) p1 += xs[n*8 + f]*w1[f];
        } else {
            p1 = P[(size_t)(base + n)*PST + 128 + c0 + c];
        }
        st[n*32 + c] = p1 + s*AGG_NORM;
    }
    __syncthreads();

    // pass 2: h = lrelu(P0 + A*t + b), with fused mean/max pool
    float bia = bias[c0 + c];
    float pm = 0.0f, px = -1e30f;
#pragma unroll 2
    for (int j = 0; j < 32; j++) {
        int n = ng*32 + j;
        const int* nbp = nbs + n*KNN;
        float s = 0.0f;
#pragma unroll
        for (int k = 0; k < KNN; k++) s += st[nbp[k]*32 + c];
        float p0;
        if (L1) {
            p0 = 0.0f;
#pragma unroll
            for (int f = 0; f < FIN; f++) p0 += xs[n*8 + f]*w0[f];
        } else {
            p0 = P[(size_t)(base + n)*PST + c0 + c];
        }
        float v = p0 + s*AGG_NORM + bia;
        v = (v > 0.0f) ? v : LEAKY*v;
        h[(size_t)(base + n)*CC + c0 + c] = v;
        pm += v; px = fmaxf(px, v);
    }

    // pool reduce across the 8 node groups
    __syncthreads();            // done gathering from st; safe to reuse s2
    s2[ng*32 + c]       = pm;
    s2[512 + ng*32 + c] = px;
    __syncthreads();
    if (ng == 0) {
        float m = 0.0f, xx = -1e30f;
#pragma unroll
        for (int q = 0; q < 8; q++) {
            m  += s2[q*32 + c];
            xx  = fmaxf(xx, s2[512 + q*32 + c]);
        }
        g[gph*C2 + layer*256 + c0 + c]       = m*(1.0f/MG);
        g[gph*C2 + layer*256 + 128 + c0 + c] = xx;
    }
}

// ---------------- double-buffered vectorized SGEMM -----------------------------
// C[M,N] = act(A[M,K] @ B + bias). SLICED: B is 3 stacked (K x BN) slices,
// grid.x selects slice; else B is K x ldb row-major shared across grid.x.
template<int BM,int BN,int BK,int TM,int TN,bool SLICED>
__global__ void __launch_bounds__((BM/TM)*(BN/TN))
sgemm_k(const float* __restrict__ A, int lda,
        const float* __restrict__ B, int ldb,
        const float* __restrict__ bias,
        float* __restrict__ C, int ldc,
        int K, int act) {
    constexpr int THREADS = (BM/TM)*(BN/TN);
    constexpr int NA = (BM*BK/4)/THREADS;
    constexpr int NB = (BK*BN/4)/THREADS;
    __shared__ float As[2][BK][BM];
    __shared__ float Bs[2][BK][BN];
    const int bm = blockIdx.y*BM;
    const int cb = blockIdx.x*BN;
    const float* Bp = SLICED ? (B + (size_t)blockIdx.x*K*BN) : (B + cb);
    const int ldbe = SLICED ? BN : ldb;
    const int tid = threadIdx.x;
    const int tx = tid % (BN/TN);
    const int ty = tid / (BN/TN);

    float4 pa[NA], pb[NB];

    auto fetch = [&](int k0) {
#pragma unroll
        for (int i = 0; i < NA; i++) {
            int e = tid + i*THREADS;
            int row = e/(BK/4), c4 = e%(BK/4);
            pa[i] = *reinterpret_cast<const float4*>(A + (size_t)(bm+row)*lda + k0 + c4*4);
        }
#pragma unroll
        for (int i = 0; i < NB; i++) {
            int e = tid + i*THREADS;
            int row = e/(BN/4), c4 = e%(BN/4);
            pb[i] = *reinterpret_cast<const float4*>(Bp + (size_t)(k0+row)*ldbe + c4*4);
        }
    };
    auto store = [&](int buf) {
#pragma unroll
        for (int i = 0; i < NA; i++) {
            int e = tid + i*THREADS;
            int row = e/(BK/4), c4 = e%(BK/4);
            As[buf][c4*4+0][row] = pa[i].x;
            As[buf][c4*4+1][row] = pa[i].y;
            As[buf][c4*4+2][row] = pa[i].z;
            As[buf][c4*4+3][row] = pa[i].w;
        }
#pragma unroll
        for (int i = 0; i < NB; i++) {
            int e = tid + i*THREADS;
            int row = e/(BN/4), c4 = e%(BN/4);
            *reinterpret_cast<float4*>(&Bs[buf][row][c4*4]) = pb[i];
        }
    };

    float acc[TM][TN] = {};
    fetch(0); store(0); __syncthreads();
    const int nk = K/BK;
    for (int kt = 0; kt < nk; kt++) {
        int buf = kt & 1;
        if (kt + 1 < nk) fetch((kt+1)*BK);
#pragma unroll
        for (int kk = 0; kk < BK; kk++) {
            float ra[TM], rb[TN];
#pragma unroll
            for (int i = 0; i < TM; i++) ra[i] = As[buf][kk][ty*TM + i];
#pragma unroll
            for (int j = 0; j < TN; j++) rb[j] = Bs[buf][kk][tx*TN + j];
#pragma unroll
            for (int i = 0; i < TM; i++)
#pragma unroll
                for (int j = 0; j < TN; j++) acc[i][j] += ra[i]*rb[j];
        }
        if (kt + 1 < nk) { store(1 - buf); __syncthreads(); }
    }
#pragma unroll
    for (int i = 0; i < TM; i++) {
        int gr = bm + ty*TM + i;
#pragma unroll
        for (int j = 0; j < TN; j += 4) {
            float4 v;
            float* vv = reinterpret_cast<float*>(&v);
#pragma unroll
            for (int q = 0; q < 4; q++) {
                int gc = cb + tx*TN + j + q;
                float u = acc[i][j+q];
                if (bias) u += bias[gc];
                if (act)  u = (u > 0.0f) ? u : LEAKY*u;
                vv[q] = u;
            }
            *reinterpret_cast<float4*>(&C[(size_t)gr*ldc + cb + tx*TN + j]) = v;
        }
    }
}

// ---------------- batch-norm: one block per channel -----------------------------
__global__ void bn_kernel(float* __restrict__ g, const float* __restrict__ gamma,
                          const float* __restrict__ beta) {
    __shared__ float red[256];
    int c = blockIdx.x, t = threadIdx.x;   // 256 threads
    float v = g[t*C2 + c];
    red[t] = v; __syncthreads();
    for (int s = 128; s > 0; s >>= 1) { if (t < s) red[t] += red[t+s]; __syncthreads(); }
    float mu = red[0]*(1.0f/NBATCH);
    __syncthreads();
    float d = v - mu;
    red[t] = d*d; __syncthreads();
    for (int s = 128; s > 0; s >>= 1) { if (t < s) red[t] += red[t+s]; __syncthreads(); }
    float var = red[0]*(1.0f/NBATCH);
    float sc = rsqrtf(var + 1e-5f)*gamma[c];
    g[t*C2 + c] = (v - mu)*sc + beta[c];
}

// ---------------- head: (256,768)@(768,3) + tanh on cols 0,1 --------------------
__global__ void head_kernel(const float* __restrict__ g, const float* __restrict__ Wo,
                            const float* __restrict__ bo, float* __restrict__ y) {
    int b = blockIdx.x;
    int w = threadIdx.y;   // 0..2
    int l = threadIdx.x;   // 0..31
    float s = 0.0f;
    for (int f = l; f < C2; f += 32) s += g[b*C2 + f]*Wo[f*3 + w];
#pragma unroll
    for (int o = 16; o; o >>= 1) s += __shfl_down_sync(0xffffffff, s, o);
    if (l == 0) {
        float v = s + bo[w];
        if (w < 2) v = tanhf(v);
        y[b*3 + w] = v;
    }
}

// ---------------- launch ---------------------------------------------------------
extern "C" void kernel_launch(void* const* d_in, const int* in_sizes, int n_in,
                              void* d_out, int out_size) {
    const float* x   = (const float*)d_in[0];
    const float* Wc1 = (const float*)d_in[1];  const float* bc1 = (const float*)d_in[2];
    const float* Wc2 = (const float*)d_in[3];  const float* bc2 = (const float*)d_in[4];
    const float* Wc3 = (const float*)d_in[5];  const float* bc3 = (const float*)d_in[6];
    const float* bng = (const float*)d_in[7];  const float* bnb = (const float*)d_in[8];
    const float* Wm[5]; const float* bm[5];
    for (int i = 0; i < 5; i++) { Wm[i] = (const float*)d_in[9+2*i]; bm[i] = (const float*)d_in[10+2*i]; }
    const float* Wo = (const float*)d_in[19];  const float* bo = (const float*)d_in[20];
    float* y = (float*)d_out;

    int* knn; float *P, *h, *g1, *g2;
    cudaGetSymbolAddress((void**)&knn, g_knn);
    cudaGetSymbolAddress((void**)&P,   g_P);
    cudaGetSymbolAddress((void**)&h,   g_h);
    cudaGetSymbolAddress((void**)&g1,  g_g1);
    cudaGetSymbolAddress((void**)&g2,  g_g2);

    const int aggsm = AGG_SMEM_FLOATS*4;
    cudaFuncSetAttribute(tag_agg<true>,  cudaFuncAttributeMaxDynamicSharedMemorySize, aggsm);
    cudaFuncSetAttribute(tag_agg<false>, cudaFuncAttributeMaxDynamicSharedMemorySize, aggsm);

    // 1. kNN
    knn_kernel<<<NBATCH, MG>>>(x, knn);

    // 2. layer 1 fully fused: project(K=7) + 2-hop aggregate + lrelu + pool
    tag_agg<true><<<dim3(4, NBATCH), 256, aggsm>>>(nullptr, x, Wc1, knn, bc1, h, g1, 0);

    // 3. layer 2: P = h @ [W0|W1|W2] (sliced GEMM), fused aggregate+pool
    sgemm_k<128,128,16,8,8,true><<<dim3(3, NTOT/128), 256>>>(
        h, CC, Wc2, 0, nullptr, P, PST, CC, 0);
    tag_agg<false><<<dim3(4, NBATCH), 256, aggsm>>>(P, nullptr, nullptr, knn, bc2, h, g1, 1);

    // 4. layer 3
    sgemm_k<128,128,16,8,8,true><<<dim3(3, NTOT/128), 256>>>(
        h, CC, Wc3, 0, nullptr, P, PST, CC, 0);
    tag_agg<false><<<dim3(4, NBATCH), 256, aggsm>>>(P, nullptr, nullptr, knn, bc3, h, g1, 2);

    // 5. batch-norm
    bn_kernel<<<C2, 256>>>(g1, bng, bnb);

    // 6. MLP x5
    float* cur = g1; float* nxt = g2;
    for (int i = 0; i < 5; i++) {
        sgemm_k<32,64,16,4,4,false><<<dim3(C2/64, NBATCH/32), 128>>>(
            cur, C2, Wm[i], C2, bm[i], nxt, C2, C2, 1);
        float* tmp = cur; cur = nxt; nxt = tmp;
    }

    // 7. head + fused tanh
    head_kernel<<<NBATCH, dim3(32,3)>>>(cur, Wo, bo, y);
}

// round 5
// speedup vs baseline: 2.0110x; 1.0686x over previous
#include <cuda_runtime.h>
#include <cuda_bf16.h>
#include <cstdint>
#include <math.h>

#define NBATCH 256
#define MG     256
#define NTOT   (NBATCH*MG)      // 65536 nodes
#define KNN    15
#define FIN    7
#define CC     128
#define PST    384
#define C2     768
#define LEAKY  0.01f
#define AGG_NORM (1.0f/15.0f)

// ---------------- scratch ------------------------------------------------------
__device__ int   g_knn[NTOT*KNN];
__device__ float g_P[(size_t)NTOT*PST];
__device__ __nv_bfloat16 g_hhi[(size_t)NTOT*CC];
__device__ __nv_bfloat16 g_hlo[(size_t)NTOT*CC];
__device__ float g_pool[NBATCH*C2];
__device__ float g_gf[NBATCH*C2];
__device__ __nv_bfloat16 g_ghiA[NBATCH*C2], g_gloA[NBATCH*C2];
__device__ __nv_bfloat16 g_ghiB[NBATCH*C2], g_gloB[NBATCH*C2];
// pre-split transposed weights: [n][k] layout
__device__ __nv_bfloat16 g_WctHi[2*3*CC*CC], g_WctLo[2*3*CC*CC];   // conv2,3: rows = 384 n, cols = 128 k
__device__ __nv_bfloat16 g_WmtHi[5*C2*C2],   g_WmtLo[5*C2*C2];     // mlp: rows = 768 n, cols = 768 k

// ---------------- helpers -------------------------------------------------------
__device__ __forceinline__ uint32_t smem_u32(const void* p) {
    uint32_t a;
    asm("{ .reg .u64 t; cvta.to.shared.u64 t, %1; cvt.u32.u64 %0, t; }" : "=r"(a) : "l"(p));
    return a;
}
__device__ __forceinline__ void ldm_x4(uint32_t* r, uint32_t addr) {
    asm volatile("ldmatrix.sync.aligned.m8n8.x4.shared.b16 {%0,%1,%2,%3}, [%4];"
                 : "=r"(r[0]), "=r"(r[1]), "=r"(r[2]), "=r"(r[3]) : "r"(addr));
}
__device__ __forceinline__ void ldm_x2(uint32_t* r, uint32_t addr) {
    asm volatile("ldmatrix.sync.aligned.m8n8.x2.shared.b16 {%0,%1}, [%2];"
                 : "=r"(r[0]), "=r"(r[1]) : "r"(addr));
}
__device__ __forceinline__ void mma16816(float* c, const uint32_t* a, const uint32_t* b) {
    asm volatile("mma.sync.aligned.m16n8k16.row.col.f32.bf16.bf16.f32 "
        "{%0,%1,%2,%3}, {%4,%5,%6,%7}, {%8,%9}, {%0,%1,%2,%3};"
        : "+f"(c[0]), "+f"(c[1]), "+f"(c[2]), "+f"(c[3])
        : "r"(a[0]), "r"(a[1]), "r"(a[2]), "r"(a[3]), "r"(b[0]), "r"(b[1]));
}

// ---------------- kNN: one block per graph ---------------------------------------
__global__ void knn_kernel(const float* __restrict__ x, int* __restrict__ knn) {
    __shared__ float4 pos[MG];
    __shared__ float  sq[MG];
    int g = blockIdx.x, t = threadIdx.x;
    const float* xr = x + (size_t)(g*MG + t)*FIN;
    float4 p = make_float4(xr[0], xr[1], xr[2], xr[3]);
    pos[t] = p;
    sq[t]  = p.x*p.x + p.y*p.y + p.z*p.z + p.w*p.w;
    __syncthreads();
    float bd[KNN]; int bi[KNN];
#pragma unroll
    for (int i = 0; i < KNN; i++) { bd[i] = 1e30f; bi[i] = 0; }
    float mysq = sq[t];
    for (int j = 0; j < MG; j++) {
        if (j == t) continue;
        float4 q = pos[j];
        float d = mysq + sq[j] - 2.0f*(p.x*q.x + p.y*q.y + p.z*q.z + p.w*q.w);
        if (d < bd[KNN-1]) {
            int k = KNN-1;
            while (k > 0 && bd[k-1] > d) { bd[k] = bd[k-1]; bi[k] = bi[k-1]; k--; }
            bd[k] = d; bi[k] = j;
        }
    }
    int* out = knn + (size_t)(g*MG + t)*KNN;
#pragma unroll
    for (int i = 0; i < KNN; i++) out[i] = g*MG + bi[i];
}

// ---------------- weight prep: transpose + bf16 split ------------------------------
__global__ void wprep_conv(const float* __restrict__ W, __nv_bfloat16* __restrict__ hi,
                           __nv_bfloat16* __restrict__ lo) {
    int idx = blockIdx.x*256 + threadIdx.x;            // 3*128*128
    if (idx >= 3*CC*CC) return;
    int s = idx / (CC*CC), r = idx % (CC*CC), n = r / CC, k = r % CC;
    float v = W[(s*CC + k)*CC + n];
    __nv_bfloat16 h = __float2bfloat16(v);
    hi[idx] = h; lo[idx] = __float2bfloat16(v - __bfloat162float(h));
}
__global__ void wprep_mlp(const float* __restrict__ W, __nv_bfloat16* __restrict__ hi,
                          __nv_bfloat16* __restrict__ lo) {
    int idx = blockIdx.x*256 + threadIdx.x;            // 768*768
    if (idx >= C2*C2) return;
    int n = idx / C2, k = idx % C2;
    float v = W[k*C2 + n];
    __nv_bfloat16 h = __float2bfloat16(v);
    hi[idx] = h; lo[idx] = __float2bfloat16(v - __bfloat162float(h));
}

// ---------------- fused TAGConv aggregate + activate + pool -------------------------
// smem floats: s2[0,8192) st[8192,16384) nbs(u8)@16384 (3840B) xs after (L1 only)
template<bool L1>
__global__ void __launch_bounds__(256)
tag_agg(const float* __restrict__ P, const float* __restrict__ x,
        const float* __restrict__ Wc, const int* __restrict__ knn,
        const float* __restrict__ bias,
        __nv_bfloat16* __restrict__ hhi, __nv_bfloat16* __restrict__ hlo,
        float* __restrict__ g, int layer) {
    extern __shared__ float sm[];
    float*   s2  = sm;
    float*   st  = sm + 8192;
    uint8_t* nbs = (uint8_t*)(sm + 16384);
    float*   xs  = (float*)(nbs + 3840);

    const int c0   = blockIdx.x*32;
    const int gph  = blockIdx.y;
    const int base = gph*MG;
    const int tid  = threadIdx.x;
    const int c    = tid & 31;
    const int ng   = tid >> 5;

    for (int i = tid; i < MG*KNN; i += 256)
        nbs[i] = (uint8_t)(knn[(size_t)base*KNN + i] & (MG-1));

    float w0[FIN], w1[FIN], w2[FIN];
    if (L1) {
#pragma unroll
        for (int f = 0; f < FIN; f++) {
            w0[f] = Wc[(0*FIN + f)*CC + c0 + c];
            w1[f] = Wc[(1*FIN + f)*CC + c0 + c];
            w2[f] = Wc[(2*FIN + f)*CC + c0 + c];
        }
        for (int i = tid; i < MG*FIN; i += 256)
            xs[(i/FIN)*8 + (i%FIN)] = x[(size_t)base*FIN + i];
    }

    if (L1) {
        __syncthreads();
#pragma unroll 4
        for (int j = 0; j < 32; j++) {
            int n = ng*32 + j;
            float acc = 0.0f;
#pragma unroll
            for (int f = 0; f < FIN; f++) acc += xs[n*8 + f]*w2[f];
            s2[n*32 + c] = acc;
        }
    } else {
#pragma unroll 4
        for (int j = 0; j < 32; j++) {
            int n = ng*32 + j;
            s2[n*32 + c] = P[(size_t)(base + n)*PST + 256 + c0 + c];
        }
    }
    __syncthreads();

#pragma unroll 4
    for (int j = 0; j < 32; j++) {
        int n = ng*32 + j;
        const uint8_t* nbp = nbs + n*KNN;
        float s = 0.0f;
#pragma unroll
        for (int k = 0; k < KNN; k++) s += s2[(int)nbp[k]*32 + c];
        float p1;
        if (L1) {
            p1 = 0.0f;
#pragma unroll
            for (int f = 0; f < FIN; f++) p1 += xs[n*8 + f]*w1[f];
        } else {
            p1 = P[(size_t)(base + n)*PST + 128 + c0 + c];
        }
        st[n*32 + c] = p1 + s*AGG_NORM;
    }
    __syncthreads();

    float bia = bias[c0 + c];
    float pm = 0.0f, px = -1e30f;
#pragma unroll 4
    for (int j = 0; j < 32; j++) {
        int n = ng*32 + j;
        const uint8_t* nbp = nbs + n*KNN;
        float s = 0.0f;
#pragma unroll
        for (int k = 0; k < KNN; k++) s += st[(int)nbp[k]*32 + c];
        float p0;
        if (L1) {
            p0 = 0.0f;
#pragma unroll
            for (int f = 0; f < FIN; f++) p0 += xs[n*8 + f]*w0[f];
        } else {
            p0 = P[(size_t)(base + n)*PST + c0 + c];
        }
        float v = p0 + s*AGG_NORM + bia;
        v = (v > 0.0f) ? v : LEAKY*v;
        __nv_bfloat16 vh = __float2bfloat16(v);
        hhi[(size_t)(base + n)*CC + c0 + c] = vh;
        hlo[(size_t)(base + n)*CC + c0 + c] = __float2bfloat16(v - __bfloat162float(vh));
        pm += v; px = fmaxf(px, v);
    }

    s2[ng*32 + c]       = pm;
    s2[512 + ng*32 + c] = px;
    __syncthreads();
    if (ng == 0) {
        float m = 0.0f, xx = -1e30f;
#pragma unroll
        for (int q = 0; q < 8; q++) {
            m += s2[q*32 + c];
            xx = fmaxf(xx, s2[512 + q*32 + c]);
        }
        g[gph*C2 + layer*256 + c0 + c]       = m*(1.0f/MG);
        g[gph*C2 + layer*256 + 128 + c0 + c] = xx;
    }
}
#define AGG_SMEM_MAIN (16384*4 + 3840)
#define AGG_SMEM_L1   (AGG_SMEM_MAIN + 2048*4)

// ---------------- mma.sync bf16-split GEMM -------------------------------------------
// C[128,128] = A[128,K] @ B[128,K]^T with A = Ahi+Alo, B = Bhi+Blo (3 terms).
// 256 threads = 8 warps; warp tile 64x32 (4x4 frags of m16n8k16).
// smem tiles 128x64 bf16 padded to 72 cols (144B rows; conflict-free ldmatrix).
#define TP   72
#define SAH  0
#define SAL  18432
#define SBH  36864
#define SBL  55296
#define GEMM_SMEM 73728
template<bool MLP_EPI>
__global__ void __launch_bounds__(256)
mma_gemm(const __nv_bfloat16* __restrict__ Ahi, const __nv_bfloat16* __restrict__ Alo, int lda,
         const __nv_bfloat16* __restrict__ Bhi, const __nv_bfloat16* __restrict__ Blo, int ldb,
         int K, const float* __restrict__ bias,
         float* __restrict__ Cf, int ldc,
         __nv_bfloat16* __restrict__ Chi, __nv_bfloat16* __restrict__ Clo) {
    extern __shared__ char smc[];
    const uint32_t sb = smem_u32(smc);
    const int tid = threadIdx.x, wid = tid >> 5, lane = tid & 31;
    const int bm = blockIdx.y*128, bn = blockIdx.x*128;
    const int wm = wid & 1;          // 0,1 -> 64-row half
    const int wn = wid >> 1;         // 0..3 -> 32-col quarter

    float acc[4][4][4] = {};

    auto load_tile = [&](int dst, const __nv_bfloat16* src, int row0, int k0, int ld) {
#pragma unroll
        for (int q = tid; q < 1024; q += 256) {
            int r = q >> 3, c8 = q & 7;
            uint4 v = *reinterpret_cast<const uint4*>(src + (size_t)(row0 + r)*ld + k0 + c8*8);
            *reinterpret_cast<uint4*>(smc + dst + r*(TP*2) + c8*16) = v;
        }
    };

    // ldmatrix lane addressing
    const int ar = lane & 15, ac = (lane >> 4) << 3;              // a: row, col-block
    const int l16 = lane & 15;
    const int br = l16 & 7, bc = (l16 >> 3) << 3;                 // b: row(n), col-block(k)

    for (int k0 = 0; k0 < K; k0 += 64) {
        load_tile(SAH, Ahi, bm, k0, lda);
        load_tile(SAL, Alo, bm, k0, lda);
        load_tile(SBH, Bhi, bn, k0, ldb);
        load_tile(SBL, Blo, bn, k0, ldb);
        __syncthreads();
#pragma unroll
        for (int kk = 0; kk < 64; kk += 16) {
            uint32_t ah[4][4], al[4][4], bh[4][2], bl[4][2];
#pragma unroll
            for (int mt = 0; mt < 4; mt++) {
                uint32_t off = (wm*64 + mt*16 + ar)*(TP*2) + (kk + ac)*2;
                ldm_x4(ah[mt], sb + SAH + off);
                ldm_x4(al[mt], sb + SAL + off);
            }
#pragma unroll
            for (int nt = 0; nt < 4; nt++) {
                uint32_t off = (wn*32 + nt*8 + br)*(TP*2) + (kk + bc)*2;
                ldm_x2(bh[nt], sb + SBH + off);
                ldm_x2(bl[nt], sb + SBL + off);
            }
#pragma unroll
            for (int mt = 0; mt < 4; mt++)
#pragma unroll
                for (int nt = 0; nt < 4; nt++) {
                    mma16816(acc[mt][nt], ah[mt], bh[nt]);
                    mma16816(acc[mt][nt], ah[mt], bl[nt]);
                    mma16816(acc[mt][nt], al[mt], bh[nt]);
                }
        }
        __syncthreads();
    }

    // epilogue: c-frag: (row = lane/4 [+8], col = (lane%4)*2 [+1])
    const int er = lane >> 2, ec = (lane & 3)*2;
#pragma unroll
    for (int mt = 0; mt < 4; mt++) {
#pragma unroll
        for (int nt = 0; nt < 4; nt++) {
            int row0 = bm + wm*64 + mt*16 + er;
            int col0 = bn + wn*32 + nt*8 + ec;
#pragma unroll
            for (int half = 0; half < 2; half++) {
                int row = row0 + half*8;
                float v0 = acc[mt][nt][half*2 + 0];
                float v1 = acc[mt][nt][half*2 + 1];
                if (MLP_EPI) {
                    v0 += bias[col0];     v1 += bias[col0 + 1];
                    v0 = (v0 > 0.0f) ? v0 : LEAKY*v0;
                    v1 = (v1 > 0.0f) ? v1 : LEAKY*v1;
                    Cf[(size_t)row*ldc + col0]     = v0;
                    Cf[(size_t)row*ldc + col0 + 1] = v1;
                    __nv_bfloat16 h0 = __float2bfloat16(v0), h1 = __float2bfloat16(v1);
                    Chi[(size_t)row*ldc + col0]     = h0;
                    Chi[(size_t)row*ldc + col0 + 1] = h1;
                    Clo[(size_t)row*ldc + col0]     = __float2bfloat16(v0 - __bfloat162float(h0));
                    Clo[(size_t)row*ldc + col0 + 1] = __float2bfloat16(v1 - __bfloat162float(h1));
                } else {
                    float2 v = make_float2(v0, v1);
                    *reinterpret_cast<float2*>(&Cf[(size_t)row*ldc + col0]) = v;
                }
            }
        }
    }
}

// ---------------- batch-norm -> bf16 split -----------------------------------------
__global__ void bn_kernel(const float* __restrict__ g, const float* __restrict__ gamma,
                          const float* __restrict__ beta,
                          __nv_bfloat16* __restrict__ ohi, __nv_bfloat16* __restrict__ olo) {
    __shared__ float red[256];
    int c = blockIdx.x, t = threadIdx.x;
    float v = g[t*C2 + c];
    red[t] = v; __syncthreads();
    for (int s = 128; s > 0; s >>= 1) { if (t < s) red[t] += red[t+s]; __syncthreads(); }
    float mu = red[0]*(1.0f/NBATCH);
    __syncthreads();
    float d = v - mu;
    red[t] = d*d; __syncthreads();
    for (int s = 128; s > 0; s >>= 1) { if (t < s) red[t] += red[t+s]; __syncthreads(); }
    float var = red[0]*(1.0f/NBATCH);
    float sc = rsqrtf(var + 1e-5f)*gamma[c];
    float o = (v - mu)*sc + beta[c];
    __nv_bfloat16 oh = __float2bfloat16(o);
    ohi[t*C2 + c] = oh;
    olo[t*C2 + c] = __float2bfloat16(o - __bfloat162float(oh));
}

// ---------------- head: (256,768)@(768,3) + tanh on cols 0,1 ------------------------
__global__ void head_kernel(const float* __restrict__ g, const float* __restrict__ Wo,
                            const float* __restrict__ bo, float* __restrict__ y) {
    int b = blockIdx.x;
    int w = threadIdx.y, l = threadIdx.x;
    float s = 0.0f;
    for (int f = l; f < C2; f += 32) s += g[b*C2 + f]*Wo[f*3 + w];
#pragma unroll
    for (int o = 16; o; o >>= 1) s += __shfl_down_sync(0xffffffff, s, o);
    if (l == 0) {
        float v = s + bo[w];
        if (w < 2) v = tanhf(v);
        y[b*3 + w] = v;
    }
}

// ---------------- launch --------------------------------------------------------------
extern "C" void kernel_launch(void* const* d_in, const int* in_sizes, int n_in,
                              void* d_out, int out_size) {
    const float* x   = (const float*)d_in[0];
    const float* Wc1 = (const float*)d_in[1];  const float* bc1 = (const float*)d_in[2];
    const float* Wc2 = (const float*)d_in[3];  const float* bc2 = (const float*)d_in[4];
    const float* Wc3 = (const float*)d_in[5];  const float* bc3 = (const float*)d_in[6];
    const float* bng = (const float*)d_in[7];  const float* bnb = (const float*)d_in[8];
    const float* Wm[5]; const float* bmv[5];
    for (int i = 0; i < 5; i++) { Wm[i] = (const float*)d_in[9+2*i]; bmv[i] = (const float*)d_in[10+2*i]; }
    const float* Wo = (const float*)d_in[19];  const float* bo = (const float*)d_in[20];
    float* y = (float*)d_out;

    int* knn; float *P, *pool, *gf;
    __nv_bfloat16 *hhi, *hlo, *ghiA, *gloA, *ghiB, *gloB, *WctHi, *WctLo, *WmtHi, *WmtLo;
    cudaGetSymbolAddress((void**)&knn,  g_knn);
    cudaGetSymbolAddress((void**)&P,    g_P);
    cudaGetSymbolAddress((void**)&pool, g_pool);
    cudaGetSymbolAddress((void**)&gf,   g_gf);
    cudaGetSymbolAddress((void**)&hhi,  g_hhi);
    cudaGetSymbolAddress((void**)&hlo,  g_hlo);
    cudaGetSymbolAddress((void**)&ghiA, g_ghiA);  cudaGetSymbolAddress((void**)&gloA, g_gloA);
    cudaGetSymbolAddress((void**)&ghiB, g_ghiB);  cudaGetSymbolAddress((void**)&gloB, g_gloB);
    cudaGetSymbolAddress((void**)&WctHi, g_WctHi); cudaGetSymbolAddress((void**)&WctLo, g_WctLo);
    cudaGetSymbolAddress((void**)&WmtHi, g_WmtHi); cudaGetSymbolAddress((void**)&WmtLo, g_WmtLo);

    cudaFuncSetAttribute(tag_agg<true>,  cudaFuncAttributeMaxDynamicSharedMemorySize, AGG_SMEM_L1);
    cudaFuncSetAttribute(tag_agg<false>, cudaFuncAttributeMaxDynamicSharedMemorySize, AGG_SMEM_MAIN);
    cudaFuncSetAttribute(mma_gemm<false>, cudaFuncAttributeMaxDynamicSharedMemorySize, GEMM_SMEM);
    cudaFuncSetAttribute(mma_gemm<true>,  cudaFuncAttributeMaxDynamicSharedMemorySize, GEMM_SMEM);

    // 0. weight prep (transpose + bf16 split)
    wprep_conv<<<(3*CC*CC + 255)/256, 256>>>(Wc2, WctHi, WctLo);
    wprep_conv<<<(3*CC*CC + 255)/256, 256>>>(Wc3, WctHi + 3*CC*CC, WctLo + 3*CC*CC);
    for (int i = 0; i < 5; i++)
        wprep_mlp<<<(C2*C2 + 255)/256, 256>>>(Wm[i], WmtHi + (size_t)i*C2*C2, WmtLo + (size_t)i*C2*C2);

    // 1. kNN
    knn_kernel<<<NBATCH, MG>>>(x, knn);

    // 2. layer 1 fused (projection inline from x)
    tag_agg<true><<<dim3(4, NBATCH), 256, AGG_SMEM_L1>>>(nullptr, x, Wc1, knn, bc1, hhi, hlo, pool, 0);

    // 3. layer 2: tensor GEMM P = h @ [W0|W1|W2], then fused agg+pool
    mma_gemm<false><<<dim3(3, NTOT/128), 256, GEMM_SMEM>>>(
        hhi, hlo, CC, WctHi, WctLo, CC, CC, nullptr, P, PST, nullptr, nullptr);
    tag_agg<false><<<dim3(4, NBATCH), 256, AGG_SMEM_MAIN>>>(P, nullptr, nullptr, knn, bc2, hhi, hlo, pool, 1);

    // 4. layer 3
    mma_gemm<false><<<dim3(3, NTOT/128), 256, GEMM_SMEM>>>(
        hhi, hlo, CC, WctHi + 3*CC*CC, WctLo + 3*CC*CC, CC, CC, nullptr, P, PST, nullptr, nullptr);
    tag_agg<false><<<dim3(4, NBATCH), 256, AGG_SMEM_MAIN>>>(P, nullptr, nullptr, knn, bc3, hhi, hlo, pool, 2);

    // 5. batch-norm -> bf16 split
    bn_kernel<<<C2, 256>>>(pool, bng, bnb, ghiA, gloA);

    // 6. MLP x5 (tensor GEMM), ping-pong A/B
    __nv_bfloat16 *chi = ghiA, *clo = gloA, *nhi = ghiB, *nlo = gloB;
    for (int i = 0; i < 5; i++) {
        mma_gemm<true><<<dim3(C2/128, NBATCH/128), 256, GEMM_SMEM>>>(
            chi, clo, C2, WmtHi + (size_t)i*C2*C2, WmtLo + (size_t)i*C2*C2, C2,
            C2, bmv[i], gf, C2, nhi, nlo);
        __nv_bfloat16* t1 = chi; chi = nhi; nhi = t1;
        __nv_bfloat16* t2 = clo; clo = nlo; nlo = t2;
    }

    // 7. head + fused tanh
    head_kernel<<<NBATCH, dim3(32, 3)>>>(gf, Wo, bo, y);
}